// round 2
// baseline (speedup 1.0000x reference)
#include <cuda_runtime.h>

constexpr int PB = 2, PC = 64, PH = 256, PW = 256, IMG = 512;

// Scratch (device globals)
__device__ float g_R[PB * 3 * PH * PW];   // resized img * identity (3 ch), 1.5 MB
__device__ float g_S[PB * PH * PW];       // inp . w_comp
__device__ float g_PXt[PW * 32];          // pos basis, transposed [w][o]
__device__ float g_PYt[PH * 32];          // [h][o]
__device__ float g_T1[PW * PH];           // T1[w][h] = sum_o PX[o,w]*PY[o,h]
__device__ float g_GX[3 * PW];            // GX[d][w] = sum_o PX[o,w+dj]*PX[o,w], dj=2(d-1) clamped
__device__ float g_GY[3 * PH];
__device__ float g_M[9];                  // w_img^T w_img (3x3)

// ---------------------------------------------------------------------------
// K1: positional basis tables (transposed layout for fast dots)
// ---------------------------------------------------------------------------
__global__ void pos_kernel(const float* __restrict__ wp) {
    int idx = blockIdx.x * 256 + threadIdx.x;   // 512 threads
    if (idx >= 512) return;
    int p = idx & 255, half = idx >> 8;
    const float kexp = -0.28782313662425575f;   // -ln(10000)/32
    float s[16], c[16];
#pragma unroll
    for (int i = 0; i < 16; i++) {
        float dv = __expf((float)(2 * i) * kexp);
        __sincosf((float)p * dv, &s[i], &c[i]);
    }
    float* dst = half ? g_PYt : g_PXt;
    int cbase = half ? 32 : 0;
#pragma unroll
    for (int o = 0; o < 32; o++) {
        float a = 0.f;
#pragma unroll
        for (int i = 0; i < 16; i++)
            a += wp[o * 64 + cbase + 2 * i] * s[i] + wp[o * 64 + cbase + 2 * i + 1] * c[i];
        dst[p * 32 + o] = a;
    }
}

// ---------------------------------------------------------------------------
// K2: gram tables T1, GX, GY, M
// ---------------------------------------------------------------------------
__global__ void tables_kernel(const float* __restrict__ w_img) {
    int bx = blockIdx.x, t = threadIdx.x;
    if (bx < 256) {
        const float* px = g_PXt + bx * 32;
        const float* py = g_PYt + t * 32;
        float a = 0.f;
#pragma unroll
        for (int o = 0; o < 32; o++) a += px[o] * py[o];
        g_T1[bx * 256 + t] = a;
    } else {
#pragma unroll
        for (int d = 0; d < 3; d++) {
            int q = min(max(t + 2 * (d - 1), 0), 255);
            float ax = 0.f, ay = 0.f;
#pragma unroll
            for (int o = 0; o < 32; o++) {
                ax += g_PXt[q * 32 + o] * g_PXt[t * 32 + o];
                ay += g_PYt[q * 32 + o] * g_PYt[t * 32 + o];
            }
            g_GX[d * 256 + t] = ax;
            g_GY[d * 256 + t] = ay;
        }
        if (t < 9) {
            int i = t / 3, j = t % 3;
            float a = 0.f;
#pragma unroll
            for (int o = 0; o < 32; o++) a += w_img[o * 3 + i] * w_img[o * 3 + j];
            g_M[t] = a;
        }
    }
}

// ---------------------------------------------------------------------------
// K3: bilinear-resize (antialias 512->256: taps {1/8,3/8,3/8,1/8}, borders
//     renormalized {3/7,3/7,1/7}) -> g_R (3 ch);  S = inp . w_comp -> g_S
// ---------------------------------------------------------------------------
__device__ __forceinline__ void make_taps(int o, int* j, float* wt) {
    j[0] = 2 * o - 1; j[1] = 2 * o; j[2] = 2 * o + 1; j[3] = 2 * o + 2;
    wt[0] = 0.125f; wt[1] = 0.375f; wt[2] = 0.375f; wt[3] = 0.125f;
    if (o == 0) {
        j[0] = 0; wt[0] = 0.f;
        wt[1] = 3.f / 7.f; wt[2] = 3.f / 7.f; wt[3] = 1.f / 7.f;
    } else if (o == 255) {
        j[3] = 511; wt[3] = 0.f;
        wt[0] = 1.f / 7.f; wt[1] = 3.f / 7.f; wt[2] = 3.f / 7.f;
    }
}

__global__ __launch_bounds__(256) void e_kernel(
    const float* __restrict__ inp, const float* __restrict__ img,
    const float* __restrict__ w_comp)
{
    int idx = blockIdx.x * blockDim.x + threadIdx.x;
    int b = idx >> 16;
    int h = (idx >> 8) & 255;
    int w = idx & 255;

    int jh[4], jw[4]; float wh[4], ww[4];
    make_taps(h, jh, wh);
    make_taps(w, jw, ww);

#pragma unroll
    for (int c = 0; c < 3; c++) {
        const float* ip = img + (b * 3 + c) * IMG * IMG;
        float acc = 0.f;
#pragma unroll
        for (int a = 0; a < 4; a++) {
            float row = 0.f;
#pragma unroll
            for (int t = 0; t < 4; t++) row += ww[t] * ip[jh[a] * IMG + jw[t]];
            acc += wh[a] * row;
        }
        g_R[((b * 3 + c) * PH + h) * PW + w] = acc;
    }

    const float* ip2 = inp + b * PC * PH * PW + h * PW + w;
    float s = 0.f;
#pragma unroll
    for (int c = 0; c < PC; c++) s += w_comp[c] * ip2[c * (PH * PW)];
    g_S[b * PH * PW + h * PW + w] = s;
}

// ---------------------------------------------------------------------------
// K4: main fused kernel.
//   fs[k] = r_nbr . (M r_ctr) + GX[dj][w] + GY[di][h] + T1[w+dj][h] + T1[w][h+di]
//   phi[k] = fs[k] * sigmoid(S_nbr);  out[c] = sum_k phi[k] * inp[c, nbr_k]
//   OOB neighbors implicitly zeroed by zero-filled inp halo.
// ---------------------------------------------------------------------------
constexpr int TW = 32, TH = 8;
constexpr int SW = TW + 4, SH = TH + 4;   // 36 x 12
constexpr int CCH = 16;

__global__ __launch_bounds__(256) void main_kernel(
    const float* __restrict__ inp, float* __restrict__ out)
{
    const int b  = blockIdx.z;
    const int h0 = blockIdx.y * TH;
    const int w0 = blockIdx.x * TW;
    const int tid = threadIdx.x;
    const int tx = tid & 31;
    const int ty = tid >> 5;

    __shared__ float sR[3][SH][SW];
    __shared__ float sS[SH][SW];
    __shared__ float sT[CCH][SH][SW];

    // load rimg (3 ch) + S tiles, zero-filled halo
    for (int i = tid; i < 4 * SH * SW; i += 256) {
        int c = i / (SH * SW);
        int rem = i % (SH * SW);
        int r = rem / SW, cc = rem % SW;
        int gh = h0 - 2 + r, gw = w0 - 2 + cc;
        float v = 0.f;
        if ((unsigned)gh < PH && (unsigned)gw < PW)
            v = (c < 3) ? g_R[((b * 3 + c) * PH + gh) * PW + gw]
                        : g_S[(b * PH + gh) * PW + gw];
        if (c < 3) sR[c][r][cc] = v; else sS[r][cc] = v;
    }
    __syncthreads();

    const int h = h0 + ty, w = w0 + tx;

    float r0 = sR[0][ty + 2][tx + 2];
    float r1 = sR[1][ty + 2][tx + 2];
    float r2 = sR[2][ty + 2][tx + 2];
    float mc0 = __ldg(&g_M[0]) * r0 + __ldg(&g_M[1]) * r1 + __ldg(&g_M[2]) * r2;
    float mc1 = __ldg(&g_M[3]) * r0 + __ldg(&g_M[4]) * r1 + __ldg(&g_M[5]) * r2;
    float mc2 = __ldg(&g_M[6]) * r0 + __ldg(&g_M[7]) * r1 + __ldg(&g_M[8]) * r2;

    float phi[9];
#pragma unroll
    for (int k = 0; k < 9; k++) {
        int di = (k / 3) * 2, dj = (k % 3) * 2;
        float fs = sR[0][ty + di][tx + dj] * mc0
                 + sR[1][ty + di][tx + dj] * mc1
                 + sR[2][ty + di][tx + dj] * mc2;
        int hc = min(max(h + di - 2, 0), PH - 1);
        int wc = min(max(w + dj - 2, 0), PW - 1);
        fs += __ldg(&g_GX[(k % 3) * PW + w]) + __ldg(&g_GY[(k / 3) * PH + h]);
        fs += __ldg(&g_T1[wc * PH + h]) + __ldg(&g_T1[w * PH + hc]);
        float s = sS[ty + di][tx + dj];
        phi[k] = fs * (1.f / (1.f + __expf(-s)));
    }

    // weighted feature aggregation over 64 channels, 16-ch chunks
    for (int ch0 = 0; ch0 < PC; ch0 += CCH) {
        __syncthreads();
        for (int i = tid; i < CCH * SH * SW; i += 256) {
            int c = i / (SH * SW);
            int rem = i % (SH * SW);
            int r = rem / SW, cc = rem % SW;
            int gh = h0 - 2 + r, gw = w0 - 2 + cc;
            float v = 0.f;
            if ((unsigned)gh < PH && (unsigned)gw < PW)
                v = inp[((b * PC + ch0 + c) * PH + gh) * PW + gw];
            sT[c][r][cc] = v;
        }
        __syncthreads();
#pragma unroll
        for (int c = 0; c < CCH; c++) {
            float acc = 0.f;
#pragma unroll
            for (int k = 0; k < 9; k++)
                acc += phi[k] * sT[c][ty + (k / 3) * 2][tx + (k % 3) * 2];
            out[((b * PC + ch0 + c) * PH + h) * PW + w] = acc;
        }
    }
}

// ---------------------------------------------------------------------------
extern "C" void kernel_launch(void* const* d_in, const int* in_sizes, int n_in,
                              void* d_out, int out_size)
{
    const float* inp    = (const float*)d_in[0];   // [2,64,256,256]
    const float* img    = (const float*)d_in[1];   // [2,3,512,512]
    const float* w_pos  = (const float*)d_in[2];   // [32,64]
    const float* w_img  = (const float*)d_in[3];   // [32,3]
    const float* w_comp = (const float*)d_in[4];   // [64]
    float* out = (float*)d_out;

    pos_kernel<<<2, 256>>>(w_pos);
    tables_kernel<<<257, 256>>>(w_img);
    e_kernel<<<(PB * PH * PW) / 256, 256>>>(inp, img, w_comp);
    dim3 grid(PW / TW, PH / TH, PB);
    main_kernel<<<grid, 256>>>(inp, out);
}

// round 3
// speedup vs baseline: 2.3154x; 2.3154x over previous
#include <cuda_runtime.h>

constexpr int PB = 2, PC = 64, PH = 256, PW = 256, IMG = 512;

// Scratch (device globals)
__device__ float g_R[PB * 3 * PH * PW];   // resized img (3 ch), [b][c][h][w]
__device__ float g_S[PB * PH * PW];       // inp . w_comp
__device__ float g_PXo[32 * PW];          // pos basis [o][w]
__device__ float g_PYo[32 * PH];          // [o][h]
__device__ float g_T1t[PH * PW];          // T1t[h][w] = sum_o PX[o,w]*PY[o,h]
__device__ float g_GX[3 * PW];            // GX[d][w] = sum_o PX[o,clamp(w+2(d-1))]*PX[o,w]
__device__ float g_GY[3 * PH];
__device__ float g_M[9];                  // w_img^T w_img

// ---------------------------------------------------------------------------
// K1: positional basis. 512 blocks x 32 threads; block=(p,half), thread=o.
// ---------------------------------------------------------------------------
__global__ void pos_kernel(const float* __restrict__ wp) {
    int p = blockIdx.x & 255;
    int half = blockIdx.x >> 8;      // 0=X, 1=Y
    int o = threadIdx.x;             // 0..31
    const float kexp = -0.28782313662425575f;  // -ln(10000)/32
    float acc = 0.f;
    int cbase = half ? 32 : 0;
#pragma unroll
    for (int i = 0; i < 16; i++) {
        float dv = __expf((float)(2 * i) * kexp);
        float s, c;
        __sincosf((float)p * dv, &s, &c);
        acc += wp[o * 64 + cbase + 2 * i] * s + wp[o * 64 + cbase + 2 * i + 1] * c;
    }
    if (half == 0) g_PXo[o * 256 + p] = acc;
    else           g_PYo[o * 256 + p] = acc;
}

// ---------------------------------------------------------------------------
// K2: gram tables (coalesced).  blocks 0..255: T1t row h; 256: GX/GY; 257: M.
// ---------------------------------------------------------------------------
__global__ void tables_kernel(const float* __restrict__ w_img) {
    int bx = blockIdx.x, t = threadIdx.x;
    if (bx < 256) {
        __shared__ float sPY[32];
        if (t < 32) sPY[t] = g_PYo[t * 256 + bx];
        __syncthreads();
        float a = 0.f;
#pragma unroll
        for (int o = 0; o < 32; o++) a += sPY[o] * g_PXo[o * 256 + t];
        g_T1t[bx * 256 + t] = a;
    } else if (bx == 256) {
#pragma unroll
        for (int d = 0; d < 3; d++) {
            int q = min(max(t + 2 * (d - 1), 0), 255);
            float ax = 0.f, ay = 0.f;
#pragma unroll
            for (int o = 0; o < 32; o++) {
                ax += g_PXo[o * 256 + q] * g_PXo[o * 256 + t];
                ay += g_PYo[o * 256 + q] * g_PYo[o * 256 + t];
            }
            g_GX[d * 256 + t] = ax;
            g_GY[d * 256 + t] = ay;
        }
    } else {
        if (t < 9) {
            int i = t / 3, j = t % 3;
            float a = 0.f;
#pragma unroll
            for (int o = 0; o < 32; o++) a += w_img[o * 3 + i] * w_img[o * 3 + j];
            g_M[t] = a;
        }
    }
}

// ---------------------------------------------------------------------------
// K3: bilinear resize 512->256 (antialias: {1/8,3/8,3/8,1/8}, borders {3/7,3/7,1/7})
//     grid 1536 = (b*3+c)*256 + h; thread = w.
// ---------------------------------------------------------------------------
__device__ __forceinline__ void make_taps(int o, int* j, float* wt) {
    j[0] = 2 * o - 1; j[1] = 2 * o; j[2] = 2 * o + 1; j[3] = 2 * o + 2;
    wt[0] = 0.125f; wt[1] = 0.375f; wt[2] = 0.375f; wt[3] = 0.125f;
    if (o == 0) {
        j[0] = 0; wt[0] = 0.f;
        wt[1] = 3.f / 7.f; wt[2] = 3.f / 7.f; wt[3] = 1.f / 7.f;
    } else if (o == 255) {
        j[3] = 511; wt[3] = 0.f;
        wt[0] = 1.f / 7.f; wt[1] = 3.f / 7.f; wt[2] = 3.f / 7.f;
    }
}

__global__ __launch_bounds__(256) void resize_kernel(const float* __restrict__ img) {
    int h = blockIdx.x & 255;
    int bc = blockIdx.x >> 8;        // 0..5 = b*3+c
    int w = threadIdx.x;
    int jh[4], jw[4]; float wh[4], ww[4];
    make_taps(h, jh, wh);
    make_taps(w, jw, ww);
    const float* ip = img + bc * IMG * IMG;
    float acc = 0.f;
#pragma unroll
    for (int a = 0; a < 4; a++) {
        float row = 0.f;
#pragma unroll
        for (int t = 0; t < 4; t++) row += ww[t] * __ldg(&ip[jh[a] * IMG + jw[t]]);
        acc += wh[a] * row;
    }
    g_R[(bc * 256 + h) * 256 + w] = acc;
}

// ---------------------------------------------------------------------------
// K4: S = inp . w_comp, float4 (4 pixels / thread)
// ---------------------------------------------------------------------------
__global__ __launch_bounds__(256) void s_kernel(
    const float* __restrict__ inp, const float* __restrict__ w_comp)
{
    int idx = blockIdx.x * 256 + threadIdx.x;     // 0..32767
    int b = idx >> 14;
    int rem4 = idx & 16383;                       // pixel4 index within batch
    const float4* ip = (const float4*)(inp + b * PC * PH * PW) + rem4;
    float4 acc = make_float4(0.f, 0.f, 0.f, 0.f);
#pragma unroll
    for (int c = 0; c < PC; c++) {
        float wc = __ldg(&w_comp[c]);
        float4 v = __ldg(&ip[c * 16384]);
        acc.x += wc * v.x; acc.y += wc * v.y; acc.z += wc * v.z; acc.w += wc * v.w;
    }
    ((float4*)(g_S + b * PH * PW))[rem4] = acc;
}

// ---------------------------------------------------------------------------
// K5: main fused kernel.  Tile 28(w) x 8(h); smem tile 32 x 12 (pow-2 width).
//   cc = tid&31 (constant column per thread), r = tid>>5 (+8).
// ---------------------------------------------------------------------------
constexpr int TW = 28, TH = 8;
constexpr int SW = 32, SH = 12;
constexpr int CCH = 8;

__global__ __launch_bounds__(256) void main_kernel(
    const float* __restrict__ inp, float* __restrict__ out)
{
    const int b  = blockIdx.z;
    const int h0 = blockIdx.y * TH;
    const int w0 = blockIdx.x * TW;
    const int tid = threadIdx.x;
    const int tx = tid & 31;      // == cc
    const int ty = tid >> 5;      // == rbase, 0..7

    __shared__ float sR[3][SH][SW];
    __shared__ float sS[SH][SW];
    __shared__ float sT1[SH][SW];
    __shared__ float sT[CCH][SH][SW];

    const int gw = w0 - 2 + tx;
    const bool vw = (unsigned)gw < (unsigned)PW;
    const int gh0 = h0 - 2 + ty;           // row r=ty
    const int gh1 = gh0 + 8;               // row r=ty+8 (only ty<4)
    const bool vh0 = (unsigned)gh0 < (unsigned)PH;
    const bool vh1 = (unsigned)gh1 < (unsigned)PH;

    // ---- stage R(3), S, T1 tiles (zero/garbage-safe halo) ----
    {
        const float* planes[5] = {
            g_R + (b * 3 + 0) * PH * PW, g_R + (b * 3 + 1) * PH * PW,
            g_R + (b * 3 + 2) * PH * PW, g_S + b * PH * PW, g_T1t };
        float* dsts[5] = { &sR[0][0][0], &sR[1][0][0], &sR[2][0][0],
                           &sS[0][0], &sT1[0][0] };
#pragma unroll
        for (int p = 0; p < 5; p++) {
            float v0 = (vw && vh0) ? __ldg(&planes[p][(gh0 << 8) + gw]) : 0.f;
            dsts[p][ty * SW + tx] = v0;
            if (ty < 4) {
                float v1 = (vw && vh1) ? __ldg(&planes[p][(gh1 << 8) + gw]) : 0.f;
                dsts[p][(ty + 8) * SW + tx] = v1;
            }
        }
    }
    __syncthreads();

    const bool active = (tx < TW) && (w0 + tx < PW);
    const int h = h0 + ty, w = w0 + tx;

    float phi[9];
    if (active) {
        float r0 = sR[0][ty + 2][tx + 2];
        float r1 = sR[1][ty + 2][tx + 2];
        float r2 = sR[2][ty + 2][tx + 2];
        float mc0 = __ldg(&g_M[0]) * r0 + __ldg(&g_M[1]) * r1 + __ldg(&g_M[2]) * r2;
        float mc1 = __ldg(&g_M[3]) * r0 + __ldg(&g_M[4]) * r1 + __ldg(&g_M[5]) * r2;
        float mc2 = __ldg(&g_M[6]) * r0 + __ldg(&g_M[7]) * r1 + __ldg(&g_M[8]) * r2;
#pragma unroll
        for (int k = 0; k < 9; k++) {
            const int row = ty + 2 * (k / 3);
            const int col = tx + 2 * (k % 3);
            float fs = sR[0][row][col] * mc0 + sR[1][row][col] * mc1
                     + sR[2][row][col] * mc2;
            fs += __ldg(&g_GX[(k % 3) * 256 + w]) + __ldg(&g_GY[(k / 3) * 256 + h]);
            fs += sT1[ty + 2][col] + sT1[row][tx + 2];
            float s = sS[row][col];
            phi[k] = fs * (1.f / (1.f + __expf(-s)));
        }
    }

    // ---- aggregation over 64 channels in CCH chunks ----
    const int ibase = (b * PC) << 16;                 // + (ch)<<16 + (gh<<8)+gw
    const int obase = ((b * PC) << 16) + (h << 8) + w;

    for (int ch0 = 0; ch0 < PC; ch0 += CCH) {
        __syncthreads();
#pragma unroll
        for (int c = 0; c < CCH; c++) {
            int cofs = ibase + ((ch0 + c) << 16);
            float v0 = (vw && vh0) ? __ldg(&inp[cofs + (gh0 << 8) + gw]) : 0.f;
            sT[c][ty][tx] = v0;
            if (ty < 4) {
                float v1 = (vw && vh1) ? __ldg(&inp[cofs + (gh1 << 8) + gw]) : 0.f;
                sT[c][ty + 8][tx] = v1;
            }
        }
        __syncthreads();
        if (active) {
#pragma unroll
            for (int c = 0; c < CCH; c++) {
                float acc = 0.f;
#pragma unroll
                for (int k = 0; k < 9; k++)
                    acc += phi[k] * sT[c][ty + 2 * (k / 3)][tx + 2 * (k % 3)];
                out[obase + ((ch0 + c) << 16)] = acc;
            }
        }
    }
}

// ---------------------------------------------------------------------------
extern "C" void kernel_launch(void* const* d_in, const int* in_sizes, int n_in,
                              void* d_out, int out_size)
{
    const float* inp    = (const float*)d_in[0];   // [2,64,256,256]
    const float* img    = (const float*)d_in[1];   // [2,3,512,512]
    const float* w_pos  = (const float*)d_in[2];   // [32,64]
    const float* w_img  = (const float*)d_in[3];   // [32,3]
    const float* w_comp = (const float*)d_in[4];   // [64]
    float* out = (float*)d_out;

    pos_kernel<<<512, 32>>>(w_pos);
    tables_kernel<<<258, 256>>>(w_img);
    resize_kernel<<<1536, 256>>>(img);
    s_kernel<<<128, 256>>>(inp, w_comp);
    dim3 grid((PW + TW - 1) / TW, PH / TH, PB);    // 10 x 32 x 2
    main_kernel<<<grid, 256>>>(inp, out);
}

// round 4
// speedup vs baseline: 2.5891x; 1.1182x over previous
#include <cuda_runtime.h>

constexpr int PB = 2, PC = 64, PH = 256, PW = 256, IMG = 512;

// Scratch (device globals)
__device__ float g_R[PB * 3 * PH * PW];   // resized img (3 ch), [b][c][h][w]
__device__ float g_S[PB * PH * PW];       // inp . w_comp
__device__ float g_PXo[32 * PW];          // pos basis [o][w]
__device__ float g_PYo[32 * PH];          // [o][h]
__device__ float g_T1t[PH * PW];          // T1t[h][w] = sum_o PX[o,w]*PY[o,h]
__device__ float g_GX[3 * PW];            // GX[d][w] = sum_o PX[o,clamp(w+2(d-1))]*PX[o,w]
__device__ float g_GY[3 * PH];
__device__ float g_M[9];                  // w_img^T w_img

// ---------------------------------------------------------------------------
// K1: positional basis. 64 blocks x 256: bx -> (o = bx>>1, half = bx&1), tid = p.
// ---------------------------------------------------------------------------
__global__ __launch_bounds__(256) void pos_kernel(const float* __restrict__ wp) {
    int o = blockIdx.x >> 1;
    int half = blockIdx.x & 1;       // 0=X, 1=Y
    int p = threadIdx.x;
    const float kexp = -0.28782313662425575f;  // -ln(10000)/32
    float acc = 0.f;
    int cbase = half ? 32 : 0;
#pragma unroll
    for (int i = 0; i < 16; i++) {
        float dv = __expf((float)(2 * i) * kexp);
        float s, c;
        __sincosf((float)p * dv, &s, &c);
        acc += wp[o * 64 + cbase + 2 * i] * s + wp[o * 64 + cbase + 2 * i + 1] * c;
    }
    if (half == 0) g_PXo[o * 256 + p] = acc;
    else           g_PYo[o * 256 + p] = acc;
}

// ---------------------------------------------------------------------------
// K2: gram tables (coalesced).  blocks 0..255: T1t row h; 256: GX/GY + M.
// ---------------------------------------------------------------------------
__global__ void tables_kernel(const float* __restrict__ w_img) {
    int bx = blockIdx.x, t = threadIdx.x;
    if (bx < 256) {
        __shared__ float sPY[32];
        if (t < 32) sPY[t] = g_PYo[t * 256 + bx];
        __syncthreads();
        float a = 0.f;
#pragma unroll
        for (int o = 0; o < 32; o++) a += sPY[o] * g_PXo[o * 256 + t];
        g_T1t[bx * 256 + t] = a;
    } else {
#pragma unroll
        for (int d = 0; d < 3; d++) {
            int q = min(max(t + 2 * (d - 1), 0), 255);
            float ax = 0.f, ay = 0.f;
#pragma unroll
            for (int o = 0; o < 32; o++) {
                ax += g_PXo[o * 256 + q] * g_PXo[o * 256 + t];
                ay += g_PYo[o * 256 + q] * g_PYo[o * 256 + t];
            }
            g_GX[d * 256 + t] = ax;
            g_GY[d * 256 + t] = ay;
        }
        if (t < 9) {
            int i = t / 3, j = t % 3;
            float a = 0.f;
#pragma unroll
            for (int o = 0; o < 32; o++) a += w_img[o * 3 + i] * w_img[o * 3 + j];
            g_M[t] = a;
        }
    }
}

// ---------------------------------------------------------------------------
// K3: prep = S map (blocks 0..511) + bilinear resize (blocks 512..2047).
//   S: 1 pixel/thread, 64 coalesced channel loads -> high MLP, full chip.
//   resize (antialias 512->256): taps {1/8,3/8,3/8,1/8}, borders {3/7,3/7,1/7}.
// ---------------------------------------------------------------------------
__device__ __forceinline__ void make_taps(int o, int* j, float* wt) {
    j[0] = 2 * o - 1; j[1] = 2 * o; j[2] = 2 * o + 1; j[3] = 2 * o + 2;
    wt[0] = 0.125f; wt[1] = 0.375f; wt[2] = 0.375f; wt[3] = 0.125f;
    if (o == 0) {
        j[0] = 0; wt[0] = 0.f;
        wt[1] = 3.f / 7.f; wt[2] = 3.f / 7.f; wt[3] = 1.f / 7.f;
    } else if (o == 255) {
        j[3] = 511; wt[3] = 0.f;
        wt[0] = 1.f / 7.f; wt[1] = 3.f / 7.f; wt[2] = 3.f / 7.f;
    }
}

__global__ __launch_bounds__(256) void prep_kernel(
    const float* __restrict__ inp, const float* __restrict__ img,
    const float* __restrict__ w_comp)
{
    int bx = blockIdx.x;
    if (bx < 512) {
        // ---- S = inp . w_comp ----
        int idx = bx * 256 + threadIdx.x;     // 0..131071
        int b = idx >> 16;
        int pix = idx & 65535;
        const float* ip = inp + ((b * PC) << 16) + pix;
        float acc = 0.f;
#pragma unroll
        for (int c = 0; c < PC; c++)
            acc += __ldg(&w_comp[c]) * __ldg(&ip[c << 16]);
        g_S[(b << 16) + pix] = acc;
    } else {
        // ---- resize ----
        int bb = bx - 512;                    // 0..1535
        int h = bb & 255;
        int bc = bb >> 8;                     // 0..5 = b*3+c
        int w = threadIdx.x;
        int jh[4], jw[4]; float wh[4], ww[4];
        make_taps(h, jh, wh);
        make_taps(w, jw, ww);
        const float* ip = img + bc * IMG * IMG;
        float acc = 0.f;
#pragma unroll
        for (int a = 0; a < 4; a++) {
            float row = 0.f;
#pragma unroll
            for (int t = 0; t < 4; t++) row += ww[t] * __ldg(&ip[jh[a] * IMG + jw[t]]);
            acc += wh[a] * row;
        }
        g_R[(bc * 256 + h) * 256 + w] = acc;
    }
}

// ---------------------------------------------------------------------------
// K4: main fused kernel.  Tile 28(w) x 8(h); smem tile 32 x 12 (pow-2 width).
// ---------------------------------------------------------------------------
constexpr int TW = 28, TH = 8;
constexpr int SW = 32, SH = 12;
constexpr int CCH = 16;

__global__ __launch_bounds__(256) void main_kernel(
    const float* __restrict__ inp, float* __restrict__ out)
{
    const int b  = blockIdx.z;
    const int h0 = blockIdx.y * TH;
    const int w0 = blockIdx.x * TW;
    const int tid = threadIdx.x;
    const int tx = tid & 31;
    const int ty = tid >> 5;      // 0..7

    __shared__ float sR[3][SH][SW];
    __shared__ float sS[SH][SW];
    __shared__ float sT1[SH][SW];
    __shared__ float sT[CCH][SH][SW];

    const int gw = w0 - 2 + tx;
    const bool vw = (unsigned)gw < (unsigned)PW;
    const int gh0 = h0 - 2 + ty;
    const int gh1 = gh0 + 8;
    const bool vh0 = (unsigned)gh0 < (unsigned)PH;
    const bool vh1 = (unsigned)gh1 < (unsigned)PH;

    // ---- stage R(3), S, T1 tiles (zero-filled halo) ----
    {
        const float* planes[5] = {
            g_R + (b * 3 + 0) * PH * PW, g_R + (b * 3 + 1) * PH * PW,
            g_R + (b * 3 + 2) * PH * PW, g_S + b * PH * PW, g_T1t };
        float* dsts[5] = { &sR[0][0][0], &sR[1][0][0], &sR[2][0][0],
                           &sS[0][0], &sT1[0][0] };
#pragma unroll
        for (int p = 0; p < 5; p++) {
            float v0 = (vw && vh0) ? __ldg(&planes[p][(gh0 << 8) + gw]) : 0.f;
            dsts[p][ty * SW + tx] = v0;
            if (ty < 4) {
                float v1 = (vw && vh1) ? __ldg(&planes[p][(gh1 << 8) + gw]) : 0.f;
                dsts[p][(ty + 8) * SW + tx] = v1;
            }
        }
    }
    __syncthreads();

    const bool active = (tx < TW) && (w0 + tx < PW);
    const int h = h0 + ty, w = w0 + tx;

    float phi[9];
    if (active) {
        float r0 = sR[0][ty + 2][tx + 2];
        float r1 = sR[1][ty + 2][tx + 2];
        float r2 = sR[2][ty + 2][tx + 2];
        float mc0 = __ldg(&g_M[0]) * r0 + __ldg(&g_M[1]) * r1 + __ldg(&g_M[2]) * r2;
        float mc1 = __ldg(&g_M[3]) * r0 + __ldg(&g_M[4]) * r1 + __ldg(&g_M[5]) * r2;
        float mc2 = __ldg(&g_M[6]) * r0 + __ldg(&g_M[7]) * r1 + __ldg(&g_M[8]) * r2;
#pragma unroll
        for (int k = 0; k < 9; k++) {
            const int row = ty + 2 * (k / 3);
            const int col = tx + 2 * (k % 3);
            float fs = sR[0][row][col] * mc0 + sR[1][row][col] * mc1
                     + sR[2][row][col] * mc2;
            fs += __ldg(&g_GX[(k % 3) * 256 + w]) + __ldg(&g_GY[(k / 3) * 256 + h]);
            fs += sT1[ty + 2][col] + sT1[row][tx + 2];
            float s = sS[row][col];
            phi[k] = fs * (1.f / (1.f + __expf(-s)));
        }
    }

    // ---- aggregation over 64 channels in CCH chunks ----
    const int ibase = (b * PC) << 16;
    const int obase = ((b * PC) << 16) + (h << 8) + w;

    for (int ch0 = 0; ch0 < PC; ch0 += CCH) {
        __syncthreads();
#pragma unroll
        for (int c = 0; c < CCH; c++) {
            int cofs = ibase + ((ch0 + c) << 16);
            float v0 = (vw && vh0) ? __ldg(&inp[cofs + (gh0 << 8) + gw]) : 0.f;
            sT[c][ty][tx] = v0;
            if (ty < 4) {
                float v1 = (vw && vh1) ? __ldg(&inp[cofs + (gh1 << 8) + gw]) : 0.f;
                sT[c][ty + 8][tx] = v1;
            }
        }
        __syncthreads();
        if (active) {
#pragma unroll
            for (int c = 0; c < CCH; c++) {
                float acc = 0.f;
#pragma unroll
                for (int k = 0; k < 9; k++)
                    acc += phi[k] * sT[c][ty + 2 * (k / 3)][tx + 2 * (k % 3)];
                out[obase + ((ch0 + c) << 16)] = acc;
            }
        }
    }
}

// ---------------------------------------------------------------------------
extern "C" void kernel_launch(void* const* d_in, const int* in_sizes, int n_in,
                              void* d_out, int out_size)
{
    const float* inp    = (const float*)d_in[0];   // [2,64,256,256]
    const float* img    = (const float*)d_in[1];   // [2,3,512,512]
    const float* w_pos  = (const float*)d_in[2];   // [32,64]
    const float* w_img  = (const float*)d_in[3];   // [32,3]
    const float* w_comp = (const float*)d_in[4];   // [64]
    float* out = (float*)d_out;

    pos_kernel<<<64, 256>>>(w_pos);
    tables_kernel<<<257, 256>>>(w_img);
    prep_kernel<<<2048, 256>>>(inp, img, w_comp);
    dim3 grid((PW + TW - 1) / TW, PH / TH, PB);    // 10 x 32 x 2
    main_kernel<<<grid, 256>>>(inp, out);
}

// round 5
// speedup vs baseline: 3.2284x; 1.2469x over previous
#include <cuda_runtime.h>

constexpr int PB = 2, PC = 64, PH = 256, PW = 256, IMG = 512;

// Scratch (device globals)
__device__ float g_R[PB * 3 * PH * PW];   // resized img (3 ch)
__device__ float g_S[PB * PH * PW];       // inp . w_comp
__device__ float g_PXo[32 * PW];          // pos basis [o][w]
__device__ float g_PYo[32 * PH];
__device__ float g_T1t[PH * PW];          // T1t[h][w] = sum_o PX[o,w]*PY[o,h]
__device__ float g_GX[3 * PW];            // GX[d][w] = sum_o PX[o,clamp(w+2(d-1))]*PX[o,w]
__device__ float g_GY[3 * PH];
__device__ float g_M[9];                  // w_img^T w_img
__device__ float g_phi[PB * 9 * PH * PW]; // per-neighbor weight, 4.7 MB

// ---------------------------------------------------------------------------
// K1: positional basis
// ---------------------------------------------------------------------------
__global__ __launch_bounds__(256) void pos_kernel(const float* __restrict__ wp) {
    int o = blockIdx.x >> 1;
    int half = blockIdx.x & 1;
    int p = threadIdx.x;
    const float kexp = -0.28782313662425575f;  // -ln(10000)/32
    float acc = 0.f;
    int cbase = half ? 32 : 0;
#pragma unroll
    for (int i = 0; i < 16; i++) {
        float dv = __expf((float)(2 * i) * kexp);
        float s, c;
        __sincosf((float)p * dv, &s, &c);
        acc += wp[o * 64 + cbase + 2 * i] * s + wp[o * 64 + cbase + 2 * i + 1] * c;
    }
    if (half == 0) g_PXo[o * 256 + p] = acc;
    else           g_PYo[o * 256 + p] = acc;
}

// ---------------------------------------------------------------------------
// K2: gram tables
// ---------------------------------------------------------------------------
__global__ void tables_kernel(const float* __restrict__ w_img) {
    int bx = blockIdx.x, t = threadIdx.x;
    if (bx < 256) {
        __shared__ float sPY[32];
        if (t < 32) sPY[t] = g_PYo[t * 256 + bx];
        __syncthreads();
        float a = 0.f;
#pragma unroll
        for (int o = 0; o < 32; o++) a += sPY[o] * g_PXo[o * 256 + t];
        g_T1t[bx * 256 + t] = a;
    } else {
#pragma unroll
        for (int d = 0; d < 3; d++) {
            int q = min(max(t + 2 * (d - 1), 0), 255);
            float ax = 0.f, ay = 0.f;
#pragma unroll
            for (int o = 0; o < 32; o++) {
                ax += g_PXo[o * 256 + q] * g_PXo[o * 256 + t];
                ay += g_PYo[o * 256 + q] * g_PYo[o * 256 + t];
            }
            g_GX[d * 256 + t] = ax;
            g_GY[d * 256 + t] = ay;
        }
        if (t < 9) {
            int i = t / 3, j = t % 3;
            float a = 0.f;
#pragma unroll
            for (int o = 0; o < 32; o++) a += w_img[o * 3 + i] * w_img[o * 3 + j];
            g_M[t] = a;
        }
    }
}

// ---------------------------------------------------------------------------
// K3: prep = S map (blocks 0..511) + bilinear resize (blocks 512..2047)
// ---------------------------------------------------------------------------
__device__ __forceinline__ void make_taps(int o, int* j, float* wt) {
    j[0] = 2 * o - 1; j[1] = 2 * o; j[2] = 2 * o + 1; j[3] = 2 * o + 2;
    wt[0] = 0.125f; wt[1] = 0.375f; wt[2] = 0.375f; wt[3] = 0.125f;
    if (o == 0) {
        j[0] = 0; wt[0] = 0.f;
        wt[1] = 3.f / 7.f; wt[2] = 3.f / 7.f; wt[3] = 1.f / 7.f;
    } else if (o == 255) {
        j[3] = 511; wt[3] = 0.f;
        wt[0] = 1.f / 7.f; wt[1] = 3.f / 7.f; wt[2] = 3.f / 7.f;
    }
}

__global__ __launch_bounds__(256) void prep_kernel(
    const float* __restrict__ inp, const float* __restrict__ img,
    const float* __restrict__ w_comp)
{
    int bx = blockIdx.x;
    if (bx < 512) {
        int idx = bx * 256 + threadIdx.x;
        int b = idx >> 16;
        int pix = idx & 65535;
        const float* ip = inp + ((b * PC) << 16) + pix;
        float acc = 0.f;
#pragma unroll
        for (int c = 0; c < PC; c++)
            acc += __ldg(&w_comp[c]) * __ldg(&ip[c << 16]);
        g_S[(b << 16) + pix] = acc;
    } else {
        int bb = bx - 512;
        int h = bb & 255;
        int bc = bb >> 8;
        int w = threadIdx.x;
        int jh[4], jw[4]; float wh[4], ww[4];
        make_taps(h, jh, wh);
        make_taps(w, jw, ww);
        const float* ip = img + bc * IMG * IMG;
        float acc = 0.f;
#pragma unroll
        for (int a = 0; a < 4; a++) {
            float row = 0.f;
#pragma unroll
            for (int t = 0; t < 4; t++) row += ww[t] * __ldg(&ip[jh[a] * IMG + jw[t]]);
            acc += wh[a] * row;
        }
        g_R[(bc * 256 + h) * 256 + w] = acc;
    }
}

// ---------------------------------------------------------------------------
// K4: phi kernel — one thread per pixel, writes g_phi[b][k][h][w].
//   OOB neighbors: clamped indices give finite garbage; aggregation's zero
//   halo on inp kills those terms, so no masking needed.
// ---------------------------------------------------------------------------
__global__ __launch_bounds__(256) void phi_kernel() {
    int idx = blockIdx.x * 256 + threadIdx.x;   // 0..131071
    int b = idx >> 16;
    int h = (idx >> 8) & 255;
    int w = idx & 255;

    const float* Rb = g_R + ((b * 3) << 16);
    const float* Sb = g_S + (b << 16);
    const int ctr = (h << 8) + w;

    float r0 = __ldg(&Rb[ctr]);
    float r1 = __ldg(&Rb[65536 + ctr]);
    float r2 = __ldg(&Rb[131072 + ctr]);
    float mc0 = __ldg(&g_M[0]) * r0 + __ldg(&g_M[1]) * r1 + __ldg(&g_M[2]) * r2;
    float mc1 = __ldg(&g_M[3]) * r0 + __ldg(&g_M[4]) * r1 + __ldg(&g_M[5]) * r2;
    float mc2 = __ldg(&g_M[6]) * r0 + __ldg(&g_M[7]) * r1 + __ldg(&g_M[8]) * r2;

#pragma unroll
    for (int k = 0; k < 9; k++) {
        int di = (k / 3), dj = (k % 3);
        int hn = min(max(h + 2 * di - 2, 0), 255);
        int wn = min(max(w + 2 * dj - 2, 0), 255);
        int nb = (hn << 8) + wn;
        float fs = __ldg(&Rb[nb]) * mc0 + __ldg(&Rb[65536 + nb]) * mc1
                 + __ldg(&Rb[131072 + nb]) * mc2;
        fs += __ldg(&g_GX[dj * 256 + w]) + __ldg(&g_GY[di * 256 + h]);
        fs += __ldg(&g_T1t[(h << 8) + wn]) + __ldg(&g_T1t[(hn << 8) + w]);
        float s = __ldg(&Sb[nb]);
        float phi = fs * (1.f / (1.f + __expf(-s)));
        g_phi[(((b * 9 + k) << 16)) + ctr] = phi;
    }
}

// ---------------------------------------------------------------------------
// K5: aggregation.  Tile 28(w) x 8(h), 16 channels per block (4-way split).
//   grid (10, 32, 8): z = b*4 + chgroup.  ONE __syncthreads per block.
// ---------------------------------------------------------------------------
constexpr int TW = 28, TH = 8;
constexpr int SW = 32, SH = 12;
constexpr int CCH = 16;

__global__ __launch_bounds__(256) void agg_kernel(
    const float* __restrict__ inp, float* __restrict__ out)
{
    const int z  = blockIdx.z;
    const int b  = z >> 2;
    const int ch0 = (z & 3) * CCH;
    const int h0 = blockIdx.y * TH;
    const int w0 = blockIdx.x * TW;
    const int tid = threadIdx.x;
    const int tx = tid & 31;
    const int ty = tid >> 5;      // 0..7

    __shared__ float sT[CCH][SH][SW];

    const int gw = w0 - 2 + tx;
    const bool vw = (unsigned)gw < (unsigned)PW;
    const int gh0 = h0 - 2 + ty;
    const int gh1 = gh0 + 8;
    const bool vh0 = (unsigned)gh0 < (unsigned)PH;
    const bool vh1 = (unsigned)gh1 < (unsigned)PH;

    const bool active = (tx < TW) && (w0 + tx < PW);
    const int h = h0 + ty, w = w0 + tx;
    const int ctr = (h << 8) + w;

    // ---- issue all global loads up front ----
    float v0[CCH], v1[CCH];
    const int ibase = ((b * PC + ch0) << 16);
#pragma unroll
    for (int c = 0; c < CCH; c++) {
        int cofs = ibase + (c << 16);
        v0[c] = (vw && vh0) ? __ldg(&inp[cofs + (gh0 << 8) + gw]) : 0.f;
        if (ty < 4)
            v1[c] = (vw && vh1) ? __ldg(&inp[cofs + (gh1 << 8) + gw]) : 0.f;
    }
    float phi[9];
    if (active) {
        const float* pb = g_phi + ((b * 9) << 16) + ctr;
#pragma unroll
        for (int k = 0; k < 9; k++) phi[k] = __ldg(&pb[k << 16]);
    }

    // ---- stage to smem ----
#pragma unroll
    for (int c = 0; c < CCH; c++) {
        sT[c][ty][tx] = v0[c];
        if (ty < 4) sT[c][ty + 8][tx] = v1[c];
    }
    __syncthreads();

    // ---- compute ----
    if (active) {
        const int obase = ((b * PC + ch0) << 16) + ctr;
#pragma unroll
        for (int c = 0; c < CCH; c++) {
            float acc = 0.f;
#pragma unroll
            for (int k = 0; k < 9; k++)
                acc += phi[k] * sT[c][ty + 2 * (k / 3)][tx + 2 * (k % 3)];
            out[obase + (c << 16)] = acc;
        }
    }
}

// ---------------------------------------------------------------------------
extern "C" void kernel_launch(void* const* d_in, const int* in_sizes, int n_in,
                              void* d_out, int out_size)
{
    const float* inp    = (const float*)d_in[0];   // [2,64,256,256]
    const float* img    = (const float*)d_in[1];   // [2,3,512,512]
    const float* w_pos  = (const float*)d_in[2];   // [32,64]
    const float* w_img  = (const float*)d_in[3];   // [32,3]
    const float* w_comp = (const float*)d_in[4];   // [64]
    float* out = (float*)d_out;

    pos_kernel<<<64, 256>>>(w_pos);
    tables_kernel<<<257, 256>>>(w_img);
    prep_kernel<<<2048, 256>>>(inp, img, w_comp);
    phi_kernel<<<512, 256>>>();
    dim3 grid((PW + TW - 1) / TW, PH / TH, PB * 4);   // 10 x 32 x 8 = 2560
    agg_kernel<<<grid, 256>>>(inp, out);
}